// round 5
// baseline (speedup 1.0000x reference)
#include <cuda_runtime.h>
#include <cuda_bf16.h>
#include <cuda_fp16.h>
#include <cstdint>

// Problem constants
#define NB     4
#define HH     64
#define WW     64
#define EMBED  128
#define NH     4
#define HD     32
#define CTX    256
#define RANK   8
#define KER    7
#define K2     49
#define PAD    3
#define SCALE  0.17677669529663689f   // 32^-0.5
#define TOK    4096
#define NTOK   16384

// ---------------- device scratch ----------------
__device__ float g_c2[NB * RANK];
__device__ float g_qkv[3 * NB * NH * TOK * HD];               // fp32 [s][bh][tok][d]
__device__ __align__(16) unsigned short g_xh[NB * TOK * EMBED];
__device__ __align__(16) unsigned short g_xl[NB * TOK * EMBED];
__device__ __align__(16) unsigned short g_wh[NB * 3 * EMBED * EMBED];
__device__ __align__(16) unsigned short g_wl[NB * 3 * EMBED * EMBED];
__device__ __align__(16) unsigned short g_ph[EMBED * EMBED];
__device__ __align__(16) unsigned short g_pl[EMBED * EMBED];
__device__ __align__(16) unsigned short g_oh[NTOK * EMBED];
__device__ __align__(16) unsigned short g_ol[NTOK * EMBED];

// ---------------- kernel 0: c2 = alpha * (context @ Blora) -------------------
__global__ void prep_kernel(const float* __restrict__ ctx,
                            const float* __restrict__ Blora,
                            const float* __restrict__ g1w,
                            const float* __restrict__ g1b,
                            const float* __restrict__ g2w,
                            const float* __restrict__ g2b) {
    __shared__ float scp[32];
    __shared__ float sh[64];
    __shared__ float sal[4];
    int t = threadIdx.x;
    if (t < 32) {
        int b = t >> 3, r = t & 7;
        float s = 0.f;
        #pragma unroll 4
        for (int c = 0; c < CTX; ++c)
            s = fmaf(ctx[b * CTX + c], Blora[c * RANK + r], s);
        scp[t] = s;
    } else if (t >= 64) {
        int u = t - 64;
        int b = u >> 4, j = u & 15;
        float hj = g1b[j];
        #pragma unroll 4
        for (int c = 0; c < CTX; ++c)
            hj = fmaf(ctx[b * CTX + c], g1w[j * CTX + c], hj);
        sh[u] = fmaxf(hj, 0.f) * g2w[j];
    }
    __syncthreads();
    if (t < 4) {
        float s = g2b[0];
        #pragma unroll
        for (int j = 0; j < 16; ++j) s += sh[t * 16 + j];
        sal[t] = 1.f / (1.f + __expf(-s));
    }
    __syncthreads();
    if (t < 32) g_c2[t] = sal[t >> 3] * scp[t];
}

// ---------------- kernel 1: pre-split everything into bf16 hi/lo -------------
__device__ __forceinline__ void split4(float4 v, ushort4& h, ushort4& l) {
    __nv_bfloat16 hx = __float2bfloat16_rn(v.x);
    __nv_bfloat16 hy = __float2bfloat16_rn(v.y);
    __nv_bfloat16 hz = __float2bfloat16_rn(v.z);
    __nv_bfloat16 hw = __float2bfloat16_rn(v.w);
    h = make_ushort4(__bfloat16_as_ushort(hx), __bfloat16_as_ushort(hy),
                     __bfloat16_as_ushort(hz), __bfloat16_as_ushort(hw));
    l = make_ushort4(
        __bfloat16_as_ushort(__float2bfloat16_rn(v.x - __bfloat162float(hx))),
        __bfloat16_as_ushort(__float2bfloat16_rn(v.y - __bfloat162float(hy))),
        __bfloat16_as_ushort(__float2bfloat16_rn(v.z - __bfloat162float(hz))),
        __bfloat16_as_ushort(__float2bfloat16_rn(v.w - __bfloat162float(hw))));
}

// grid: [0,2048) x  | [2048,2240) Weff  | [2240,2256) Wproj
__global__ void conv_kernel(const float* __restrict__ x,
                            const float* __restrict__ Wqkv,
                            const float* __restrict__ A,
                            const float* __restrict__ Vl,
                            const float* __restrict__ Wproj) {
    int blk = blockIdx.x, tid = threadIdx.x;
    if (blk < 2048) {
        int id = blk * 256 + tid;               // 524288 float4
        float4 v = ((const float4*)x)[id];
        ushort4 h, l; split4(v, h, l);
        ((ushort4*)g_xh)[id] = h;
        ((ushort4*)g_xl)[id] = l;
    } else if (blk < 2240) {
        int id = (blk - 2048) * 256 + tid;      // 49152 float4 over [b][o][i]
        int b = id / 12288;
        int rid = id - b * 12288;
        float4 w = ((const float4*)Wqkv)[rid];
        int e0 = rid * 4;
        int o = e0 >> 7, i = e0 & 127;
        const float* c2 = g_c2 + b * RANK;
        #pragma unroll
        for (int r = 0; r < RANK; ++r) {
            float vc = Vl[o * RANK + r] * c2[r];
            w.x = fmaf(vc, A[(i + 0) * RANK + r], w.x);
            w.y = fmaf(vc, A[(i + 1) * RANK + r], w.y);
            w.z = fmaf(vc, A[(i + 2) * RANK + r], w.z);
            w.w = fmaf(vc, A[(i + 3) * RANK + r], w.w);
        }
        ushort4 h, l; split4(w, h, l);
        ((ushort4*)g_wh)[id] = h;
        ((ushort4*)g_wl)[id] = l;
    } else {
        int id = (blk - 2240) * 256 + tid;      // 4096 float4
        if (id < 4096) {
            float4 v = ((const float4*)Wproj)[id];
            ushort4 h, l; split4(v, h, l);
            ((ushort4*)g_ph)[id] = h;
            ((ushort4*)g_pl)[id] = l;
        }
    }
}

// ================== bf16x3 tensor-core GEMM (mma.sync path) ==================
#define RSTRIDE 272
#define SM_AHI  0
#define SM_ALO  (128 * RSTRIDE)
#define SM_BHI  (2 * 128 * RSTRIDE)
#define SM_BLO  (3 * 128 * RSTRIDE)
#define GEMM_SMEM (4 * 128 * RSTRIDE)   // 139264 bytes

__device__ __forceinline__ uint32_t smem_u32(const void* p) {
    uint32_t a;
    asm("{ .reg .u64 t; cvta.to.shared.u64 t, %1; cvt.u32.u64 %0, t; }"
        : "=r"(a) : "l"(p));
    return a;
}

#define LDM4(r, addr) \
    asm volatile("ldmatrix.sync.aligned.m8n8.x4.shared.b16 {%0,%1,%2,%3}, [%4];" \
        : "=r"((r)[0]), "=r"((r)[1]), "=r"((r)[2]), "=r"((r)[3]) : "r"(addr))

#define MMA_BF16(c, a, b0, b1) \
    asm volatile("mma.sync.aligned.m16n8k16.row.col.f32.bf16.bf16.f32 " \
        "{%0,%1,%2,%3}, {%4,%5,%6,%7}, {%8,%9}, {%0,%1,%2,%3};" \
        : "+f"((c)[0]), "+f"((c)[1]), "+f"((c)[2]), "+f"((c)[3]) \
        : "r"((a)[0]), "r"((a)[1]), "r"((a)[2]), "r"((a)[3]), "r"(b0), "r"(b1))

template <bool QKV>
__global__ __launch_bounds__(256, 1)
void gemm_mma(const float* __restrict__ bias, float* __restrict__ outp) {
    extern __shared__ char smem[];
    const uint32_t sbase = smem_u32(smem);
    const int tid  = threadIdx.x;
    const int wid  = tid >> 5;
    const int lane = tid & 31;
    const int mw = wid >> 1;
    const int nw = wid & 1;
    const int b  = blockIdx.z;
    const int m0 = blockIdx.x * 128;
    const int n0 = blockIdx.y * 128;

    const unsigned short* Ah;
    const unsigned short* Al;
    const unsigned short* Bh;
    const unsigned short* Bl;
    if (QKV) {
        size_t ao = ((size_t)b * TOK + m0) * EMBED;
        size_t bo = (size_t)b * 3 * EMBED * EMBED + (size_t)n0 * EMBED;
        Ah = g_xh + ao; Al = g_xl + ao;
        Bh = g_wh + bo; Bl = g_wl + bo;
    } else {
        size_t ao = (size_t)m0 * EMBED;
        Ah = g_oh + ao; Al = g_ol + ao;
        Bh = g_ph + (size_t)n0 * EMBED; Bl = g_pl + (size_t)n0 * EMBED;
    }

    // ---- fill: pure bf16 copies, 2048 uint4 per plane ----
    #pragma unroll
    for (int it = 0; it < 8; ++it) {
        int idx = it * 256 + tid;
        int row = idx >> 4, c = idx & 15;
        uint32_t d = row * RSTRIDE + c * 16;
        size_t s = (size_t)row * EMBED + c * 8;
        *(uint4*)(smem + SM_AHI + d) = *(const uint4*)(Ah + s);
        *(uint4*)(smem + SM_ALO + d) = *(const uint4*)(Al + s);
        *(uint4*)(smem + SM_BHI + d) = *(const uint4*)(Bh + s);
        *(uint4*)(smem + SM_BLO + d) = *(const uint4*)(Bl + s);
    }
    __syncthreads();

    const int arow = mw * 32 + (lane & 7) + ((lane >> 3) & 1) * 8;
    const uint32_t akb = ((lane >> 4) & 1) * 16;
    uint32_t aHi[2], aLo[2];
    #pragma unroll
    for (int mt = 0; mt < 2; ++mt) {
        uint32_t ro = (arow + mt * 16) * RSTRIDE + akb;
        aHi[mt] = sbase + SM_AHI + ro;
        aLo[mt] = sbase + SM_ALO + ro;
    }
    const int brow = nw * 64 + (lane & 7) + (lane >> 4) * 8;
    const uint32_t bkb = ((lane >> 3) & 1) * 16;
    uint32_t bHi[4], bLo[4];
    #pragma unroll
    for (int q = 0; q < 4; ++q) {
        uint32_t ro = (brow + q * 16) * RSTRIDE + bkb;
        bHi[q] = sbase + SM_BHI + ro;
        bLo[q] = sbase + SM_BLO + ro;
    }

    float acc[2][8][4];
    #pragma unroll
    for (int mt = 0; mt < 2; ++mt)
        #pragma unroll
        for (int nt = 0; nt < 8; ++nt)
            #pragma unroll
            for (int c = 0; c < 4; ++c) acc[mt][nt][c] = 0.f;

    #pragma unroll
    for (int kt = 0; kt < 8; ++kt) {
        const uint32_t ko = kt * 32;
        uint32_t ah[2][4], al[2][4], bh[4][4], bl[4][4];
        #pragma unroll
        for (int mt = 0; mt < 2; ++mt) {
            LDM4(ah[mt], aHi[mt] + ko);
            LDM4(al[mt], aLo[mt] + ko);
        }
        #pragma unroll
        for (int q = 0; q < 4; ++q) {
            LDM4(bh[q], bHi[q] + ko);
            LDM4(bl[q], bLo[q] + ko);
        }
        #pragma unroll
        for (int mt = 0; mt < 2; ++mt)
            #pragma unroll
            for (int nt = 0; nt < 8; ++nt) {
                const int q = nt >> 1, r = (nt & 1) * 2;
                MMA_BF16(acc[mt][nt], ah[mt], bh[q][r], bh[q][r + 1]);
                MMA_BF16(acc[mt][nt], ah[mt], bl[q][r], bl[q][r + 1]);
                MMA_BF16(acc[mt][nt], al[mt], bh[q][r], bh[q][r + 1]);
            }
    }

    #pragma unroll
    for (int mt = 0; mt < 2; ++mt)
        #pragma unroll
        for (int nt = 0; nt < 8; ++nt) {
            const float* c = acc[mt][nt];
            const int col = n0 + nw * 64 + nt * 8 + (lane & 3) * 2;
            const int r0  = m0 + mw * 32 + mt * 16 + (lane >> 2);
            float2 bv = *(const float2*)(bias + col);
            float2 lo = make_float2(c[0] + bv.x, c[1] + bv.y);
            float2 hi = make_float2(c[2] + bv.x, c[3] + bv.y);
            if (QKV) {
                const int s = col >> 7, hh2 = (col >> 5) & 3, d = col & 31;
                float* p0 = g_qkv + ((size_t)(s * 16 + b * 4 + hh2) * TOK + r0) * HD + d;
                *(float2*)p0 = lo;
                *(float2*)(p0 + 8 * HD) = hi;
            } else {
                float* p0 = outp + (size_t)r0 * EMBED + col;
                *(float2*)p0 = lo;
                *(float2*)(p0 + 8 * EMBED) = hi;
            }
        }
}

// ---------------- kernel 3: neighborhood attention (fp16 smem) ---------------
// tile 8x16 queries, halo 14x22. K/V stored fp16 planar: 4 planes, each plane
// holds one 16B chunk (8 halfs = 8 dims) per position. PLANE_W % 32 == 8 =>
// conflict-free STS.128/LDS.128 phases. One 19.6KB buffer reused K then V.
// exp via degree-8 expm1 polynomial (logits are tiny) -> no MUFU.
// Softmax weights u=exp(x)-1 packed fp16 pairs (25 regs).
#define TILE_I 8
#define TILE_J 16
#define HALO_I 14
#define HALO_J 22
#define NPOS   (HALO_I * HALO_J)        // 308
#define PLANE_W 1256                    // words/plane: 308*4=1232, pad to ==8 mod 32
#define ATTN_SMEM (4 * PLANE_W * 4)     // 20096 bytes

__device__ __forceinline__ __half2 u2h(uint32_t u) {
    __half2 h; *(uint32_t*)&h = u; return h;
}

__global__ __launch_bounds__(128, 6) void attn_kernel() {
    extern __shared__ float smemf[];

    const int tid = threadIdx.x;
    const int z = blockIdx.z;
    const int b = z >> 2, h = z & 3;
    const int j0 = blockIdx.x * TILE_J;
    const int i0 = blockIdx.y * TILE_I;

    const int bh = b * 4 + h;
    const float* qg = g_qkv + (size_t)bh * TOK * HD;
    const float* kg = g_qkv + (size_t)(16 + bh) * TOK * HD;
    const float* vg = g_qkv + (size_t)(32 + bh) * TOK * HD;

    const int li = tid >> 4;
    const int lj = tid & 15;
    const int gi = i0 + li, gj = j0 + lj;

    // ---- fill K halo as fp16 (zero OOB == reference zero-padding) ----
    #pragma unroll 1
    for (int idx = tid; idx < NPOS * 4; idx += 128) {
        int pos = idx >> 2, f = idx & 3;
        int r = pos / HALO_J, c = pos - r * HALO_J;
        int ri = i0 - PAD + r, rj = j0 - PAD + c;
        uint4 st = make_uint4(0u, 0u, 0u, 0u);
        if (ri >= 0 && ri < HH && rj >= 0 && rj < WW) {
            const float4* s = (const float4*)(kg + ((size_t)(ri * WW + rj)) * HD + f * 8);
            float4 a = s[0], bb = s[1];
            __half2 h0 = __floats2half2_rn(a.x, a.y);
            __half2 h1 = __floats2half2_rn(a.z, a.w);
            __half2 h2 = __floats2half2_rn(bb.x, bb.y);
            __half2 h3 = __floats2half2_rn(bb.z, bb.w);
            st.x = *(uint32_t*)&h0; st.y = *(uint32_t*)&h1;
            st.z = *(uint32_t*)&h2; st.w = *(uint32_t*)&h3;
        }
        *(uint4*)(smemf + f * PLANE_W + pos * 4) = st;
    }

    // q: fp32 -> scaled fp16 pairs
    __half2 rq[16];
    {
        const float4* qp = (const float4*)(qg + ((size_t)(gi * WW + gj)) * HD);
        #pragma unroll
        for (int q = 0; q < 8; ++q) {
            float4 v = qp[q];
            rq[2 * q]     = __floats2half2_rn(v.x * SCALE, v.y * SCALE);
            rq[2 * q + 1] = __floats2half2_rn(v.z * SCALE, v.w * SCALE);
        }
    }
    __syncthreads();

    // ---- pass 1: logits -> u = expm1(logit), packed fp16 ----
    __half2 u2[25];
    float su = 0.f;
    float upend = 0.f;
    #pragma unroll
    for (int di = 0; di < KER; ++di) {
        #pragma unroll
        for (int dj = 0; dj < KER; ++dj) {
            const int pos = (li + di) * HALO_J + (lj + dj);
            const float* pb = smemf + pos * 4;
            uint4 c0 = *(const uint4*)(pb);
            uint4 c1 = *(const uint4*)(pb + PLANE_W);
            uint4 c2 = *(const uint4*)(pb + 2 * PLANE_W);
            uint4 c3 = *(const uint4*)(pb + 3 * PLANE_W);
            __half2 d0 = __hmul2(rq[0], u2h(c0.x));
            d0 = __hfma2(rq[1],  u2h(c0.y), d0);
            d0 = __hfma2(rq[2],  u2h(c0.z), d0);
            d0 = __hfma2(rq[3],  u2h(c0.w), d0);
            __half2 d1 = __hmul2(rq[4], u2h(c1.x));
            d1 = __hfma2(rq[5],  u2h(c1.y), d1);
            d1 = __hfma2(rq[6],  u2h(c1.z), d1);
            d1 = __hfma2(rq[7],  u2h(c1.w), d1);
            __half2 d2 = __hmul2(rq[8], u2h(c2.x));
            d2 = __hfma2(rq[9],  u2h(c2.y), d2);
            d2 = __hfma2(rq[10], u2h(c2.z), d2);
            d2 = __hfma2(rq[11], u2h(c2.w), d2);
            __half2 d3 = __hmul2(rq[12], u2h(c3.x));
            d3 = __hfma2(rq[13], u2h(c3.y), d3);
            d3 = __hfma2(rq[14], u2h(c3.z), d3);
            d3 = __hfma2(rq[15], u2h(c3.w), d3);
            __half2 s2 = __hadd2(__hadd2(d0, d1), __hadd2(d2, d3));
            float xv = __low2float(s2) + __high2float(s2);
            // expm1 via degree-8 Taylor (|x| << 1): u = x * P(x)
            float t = fmaf(xv, 1.f / 40320.f, 1.f / 5040.f);
            t = fmaf(t, xv, 1.f / 720.f);
            t = fmaf(t, xv, 1.f / 120.f);
            t = fmaf(t, xv, 1.f / 24.f);
            t = fmaf(t, xv, 1.f / 6.f);
            t = fmaf(t, xv, 0.5f);
            t = fmaf(t, xv, 1.f);
            float u = xv * t;
            su += u;
            const int idx = di * KER + dj;
            if ((idx & 1) == 0) upend = u;
            else u2[idx >> 1] = __floats2half2_rn(upend, u);
        }
    }
    u2[24] = __floats2half2_rn(upend, 0.f);
    __syncthreads();

    // ---- fill V halo (same buffer) ----
    #pragma unroll 1
    for (int idx = tid; idx < NPOS * 4; idx += 128) {
        int pos = idx >> 2, f = idx & 3;
        int r = pos / HALO_J, c = pos - r * HALO_J;
        int ri = i0 - PAD + r, rj = j0 - PAD + c;
        uint4 st = make_uint4(0u, 0u, 0u, 0u);
        if (ri >= 0 && ri < HH && rj >= 0 && rj < WW) {
            const float4* s = (const float4*)(vg + ((size_t)(ri * WW + rj)) * HD + f * 8);
            float4 a = s[0], bb = s[1];
            __half2 h0 = __floats2half2_rn(a.x, a.y);
            __half2 h1 = __floats2half2_rn(a.z, a.w);
            __half2 h2 = __floats2half2_rn(bb.x, bb.y);
            __half2 h3 = __floats2half2_rn(bb.z, bb.w);
            st.x = *(uint32_t*)&h0; st.y = *(uint32_t*)&h1;
            st.z = *(uint32_t*)&h2; st.w = *(uint32_t*)&h3;
        }
        *(uint4*)(smemf + f * PLANE_W + pos * 4) = st;
    }
    __syncthreads();

    // ---- pass 2: out = sum (1+u) * v, fp32 accum ----
    float ac[32];
    #pragma unroll
    for (int d = 0; d < 32; ++d) ac[d] = 0.f;

    #pragma unroll
    for (int di = 0; di < KER; ++di) {
        #pragma unroll
        for (int dj = 0; dj < KER; ++dj) {
            const int idx = di * KER + dj;
            __half2 up = u2[idx >> 1];
            float p = 1.f + ((idx & 1) ? __high2float(up) : __low2float(up));
            const int pos = (li + di) * HALO_J + (lj + dj);
            const float* pb = smemf + pos * 4;
            #pragma unroll
            for (int f = 0; f < 4; ++f) {
                uint4 cc = *(const uint4*)(pb + f * PLANE_W);
                float2 v0 = __half22float2(u2h(cc.x));
                float2 v1 = __half22float2(u2h(cc.y));
                float2 v2 = __half22float2(u2h(cc.z));
                float2 v3 = __half22float2(u2h(cc.w));
                ac[f * 8 + 0] = fmaf(p, v0.x, ac[f * 8 + 0]);
                ac[f * 8 + 1] = fmaf(p, v0.y, ac[f * 8 + 1]);
                ac[f * 8 + 2] = fmaf(p, v1.x, ac[f * 8 + 2]);
                ac[f * 8 + 3] = fmaf(p, v1.y, ac[f * 8 + 3]);
                ac[f * 8 + 4] = fmaf(p, v2.x, ac[f * 8 + 4]);
                ac[f * 8 + 5] = fmaf(p, v2.y, ac[f * 8 + 5]);
                ac[f * 8 + 6] = fmaf(p, v3.x, ac[f * 8 + 6]);
                ac[f * 8 + 7] = fmaf(p, v3.y, ac[f * 8 + 7]);
            }
        }
    }

    const float inv = 1.f / (49.f + su);
    const size_t ob = ((size_t)(b * TOK + gi * WW + gj)) * EMBED + h * HD;
    #pragma unroll
    for (int q = 0; q < 8; ++q) {
        float o0 = ac[4 * q] * inv, o1 = ac[4 * q + 1] * inv;
        float o2 = ac[4 * q + 2] * inv, o3 = ac[4 * q + 3] * inv;
        ushort4 hi, lo;
        split4(make_float4(o0, o1, o2, o3), hi, lo);
        *(ushort4*)(g_oh + ob + 4 * q) = hi;
        *(ushort4*)(g_ol + ob + 4 * q) = lo;
    }
}

// ---------------- launch -----------------------------------------------------
extern "C" void kernel_launch(void* const* d_in, const int* in_sizes, int n_in,
                              void* d_out, int out_size) {
    const float* x     = (const float*)d_in[0];
    const float* ctx   = (const float*)d_in[1];
    const float* Wqkv  = (const float*)d_in[2];
    const float* bqkv  = (const float*)d_in[3];
    const float* A     = (const float*)d_in[4];
    const float* Blora = (const float*)d_in[5];
    const float* Vlora = (const float*)d_in[6];
    const float* g1w   = (const float*)d_in[7];
    const float* g1b   = (const float*)d_in[8];
    const float* g2w   = (const float*)d_in[9];
    const float* g2b   = (const float*)d_in[10];
    const float* Wproj = (const float*)d_in[11];
    const float* bproj = (const float*)d_in[12];
    float* out = (float*)d_out;

    cudaFuncSetAttribute(gemm_mma<true>,
                         cudaFuncAttributeMaxDynamicSharedMemorySize, GEMM_SMEM);
    cudaFuncSetAttribute(gemm_mma<false>,
                         cudaFuncAttributeMaxDynamicSharedMemorySize, GEMM_SMEM);

    prep_kernel<<<1, 128>>>(ctx, Blora, g1w, g1b, g2w, g2b);
    conv_kernel<<<2256, 256>>>(x, Wqkv, A, Vlora, Wproj);
    gemm_mma<true><<<dim3(32, 3, 4), 256, GEMM_SMEM>>>(bqkv, nullptr);
    attn_kernel<<<dim3(WW / TILE_J, HH / TILE_I, NB * NH), 128, ATTN_SMEM>>>();
    gemm_mma<false><<<dim3(128, 1, 1), 256, GEMM_SMEM>>>(bproj, out);
}

// round 8
// speedup vs baseline: 1.4947x; 1.4947x over previous
#include <cuda_runtime.h>
#include <cuda_bf16.h>
#include <cstdint>

// Problem constants
#define NB     4
#define HH     64
#define WW     64
#define EMBED  128
#define NH     4
#define HD     32
#define CTX    256
#define RANK   8
#define KER    7
#define K2     49
#define PAD    3
#define SCALE  0.17677669529663689f   // 32^-0.5
#define TOK    4096                   // tokens per batch (64*64)
#define NTOK   16384                  // total tokens

// ---------------- device scratch (static allocation: allowed) ----------------
__device__ float g_c2[NB * RANK];                 // alpha_b * c_proj[b][r]
__device__ float g_Weff[NB * 3 * EMBED * EMBED];  // [b][o][i]
__device__ float g_qkv[3 * NB * NH * TOK * HD];   // [s][b][h][tok][d]
__device__ float g_attn[NTOK * EMBED];            // [tok][h*32+d]

// ---------------- kernel 0: c2 = alpha * (context @ Blora) -------------------
__global__ void prep_kernel(const float* __restrict__ ctx,
                            const float* __restrict__ Blora,
                            const float* __restrict__ g1w,
                            const float* __restrict__ g1b,
                            const float* __restrict__ g2w,
                            const float* __restrict__ g2b) {
    __shared__ float scp[32];
    __shared__ float sh[64];
    __shared__ float sal[4];
    int t = threadIdx.x;
    if (t < 32) {
        int b = t >> 3, r = t & 7;
        float s = 0.f;
        #pragma unroll 4
        for (int c = 0; c < CTX; ++c)
            s = fmaf(ctx[b * CTX + c], Blora[c * RANK + r], s);
        scp[t] = s;
    } else if (t >= 64) {
        int u = t - 64;
        int b = u >> 4, j = u & 15;
        float hj = g1b[j];
        #pragma unroll 4
        for (int c = 0; c < CTX; ++c)
            hj = fmaf(ctx[b * CTX + c], g1w[j * CTX + c], hj);
        sh[u] = fmaxf(hj, 0.f) * g2w[j];
    }
    __syncthreads();
    if (t < 4) {
        float s = g2b[0];
        #pragma unroll
        for (int j = 0; j < 16; ++j) s += sh[t * 16 + j];
        sal[t] = 1.f / (1.f + __expf(-s));
    }
    __syncthreads();
    if (t < 32) g_c2[t] = sal[t >> 3] * scp[t];
}

// ---------------- kernel 1: W_eff = Wqkv + Vlora diag(c2) A^T ----------------
__global__ void weff_kernel(const float* __restrict__ Wqkv,
                            const float* __restrict__ A,
                            const float* __restrict__ Vl) {
    int idx = blockIdx.x * 256 + threadIdx.x;     // 4*384*128 = 196608 total
    int b = idx / (3 * EMBED * EMBED);
    int rem = idx - b * (3 * EMBED * EMBED);
    int o = rem >> 7, i = rem & 127;
    float w = Wqkv[rem];
    const float* c2 = g_c2 + b * RANK;
    #pragma unroll
    for (int r = 0; r < RANK; ++r)
        w = fmaf(Vl[o * RANK + r] * c2[r], A[i * RANK + r], w);
    g_Weff[idx] = w;
}

// ================== bf16x3 tensor-core GEMM (mma.sync path) ==================
// C[m][n] = sum_k A[m][k] * B[n][k], fp32 in/out.  a = a_hi + a_lo (bf16);
// D accumulates hh + hl + lh in fp32 (error ~2^-18 per product).
// CTA tile 128x128x128(K whole). 8 warps 4(m)x2(n), each 32x64 m16n8k16.
// Smem rows padded to 272B -> ldmatrix row addrs conflict-free, no swizzle.
#define RSTRIDE 272
#define SM_AHI  0
#define SM_ALO  (128 * RSTRIDE)
#define SM_BHI  (2 * 128 * RSTRIDE)
#define SM_BLO  (3 * 128 * RSTRIDE)
#define GEMM_SMEM (4 * 128 * RSTRIDE)   // 139264 bytes

__device__ __forceinline__ uint32_t smem_u32(const void* p) {
    uint32_t a;
    asm("{ .reg .u64 t; cvta.to.shared.u64 t, %1; cvt.u32.u64 %0, t; }"
        : "=r"(a) : "l"(p));
    return a;
}

#define LDM4(r, addr) \
    asm volatile("ldmatrix.sync.aligned.m8n8.x4.shared.b16 {%0,%1,%2,%3}, [%4];" \
        : "=r"((r)[0]), "=r"((r)[1]), "=r"((r)[2]), "=r"((r)[3]) : "r"(addr))

#define MMA_BF16(c, a, b0, b1) \
    asm volatile("mma.sync.aligned.m16n8k16.row.col.f32.bf16.bf16.f32 " \
        "{%0,%1,%2,%3}, {%4,%5,%6,%7}, {%8,%9}, {%0,%1,%2,%3};" \
        : "+f"((c)[0]), "+f"((c)[1]), "+f"((c)[2]), "+f"((c)[3]) \
        : "r"((a)[0]), "r"((a)[1]), "r"((a)[2]), "r"((a)[3]), "r"(b0), "r"(b1))

// split one float into (hi, lo) bf16 and pack pairs into u32s
__device__ __forceinline__ void split2(float x, float y, uint32_t& hi, uint32_t& lo) {
    __nv_bfloat16 hx = __float2bfloat16_rn(x);
    __nv_bfloat16 hy = __float2bfloat16_rn(y);
    __nv_bfloat16 lx = __float2bfloat16_rn(x - __bfloat162float(hx));
    __nv_bfloat16 ly = __float2bfloat16_rn(y - __bfloat162float(hy));
    hi = ((uint32_t)__bfloat16_as_ushort(hy) << 16) | __bfloat16_as_ushort(hx);
    lo = ((uint32_t)__bfloat16_as_ushort(ly) << 16) | __bfloat16_as_ushort(lx);
}

template <bool QKV>
__global__ __launch_bounds__(256, 1)
void gemm_mma(const float* __restrict__ Aglob,
              const float* __restrict__ Wglob,
              const float* __restrict__ bias,
              float* __restrict__ outp) {
    extern __shared__ char smem[];
    const uint32_t sbase = smem_u32(smem);
    const int tid  = threadIdx.x;
    const int wid  = tid >> 5;
    const int lane = tid & 31;
    const int mw = wid >> 1;          // 0..3
    const int nw = wid & 1;           // 0..1
    const int b  = blockIdx.z;
    const int m0 = blockIdx.x * 128;
    const int n0 = blockIdx.y * 128;

    const float* srcA = QKV ? Aglob + ((size_t)b * TOK + m0) * EMBED
                            : g_attn + (size_t)m0 * EMBED;
    const float* srcB = QKV ? g_Weff + (size_t)b * 3 * EMBED * EMBED + (size_t)n0 * EMBED
                            : Wglob + (size_t)n0 * EMBED;

    // ---- fill A/B tiles: fp32 -> (hi, lo) bf16 planes, 272B row stride ----
    #pragma unroll
    for (int it = 0; it < 16; ++it) {
        int idx = it * 256 + tid;            // 4096 float4 slots
        int row = idx >> 5, c4 = idx & 31;
        float4 v = *(const float4*)(srcA + (size_t)row * EMBED + c4 * 4);
        uint32_t h0, l0, h1, l1;
        split2(v.x, v.y, h0, l0);
        split2(v.z, v.w, h1, l1);
        uint32_t off = row * RSTRIDE + c4 * 8;
        *(uint2*)(smem + SM_AHI + off) = make_uint2(h0, h1);
        *(uint2*)(smem + SM_ALO + off) = make_uint2(l0, l1);
    }
    #pragma unroll
    for (int it = 0; it < 16; ++it) {
        int idx = it * 256 + tid;
        int row = idx >> 5, c4 = idx & 31;
        float4 v = *(const float4*)(srcB + (size_t)row * EMBED + c4 * 4);
        uint32_t h0, l0, h1, l1;
        split2(v.x, v.y, h0, l0);
        split2(v.z, v.w, h1, l1);
        uint32_t off = row * RSTRIDE + c4 * 8;
        *(uint2*)(smem + SM_BHI + off) = make_uint2(h0, h1);
        *(uint2*)(smem + SM_BLO + off) = make_uint2(l0, l1);
    }
    __syncthreads();

    // A x4: lanes 0-7: m0-7 k0 | 8-15: m8-15 k0 | 16-23: m0-7 k8 | 24-31: m8-15 k8
    const int arow = mw * 32 + (lane & 7) + ((lane >> 3) & 1) * 8;
    const uint32_t akb = ((lane >> 4) & 1) * 16;
    uint32_t aHi[2], aLo[2];
    #pragma unroll
    for (int mt = 0; mt < 2; ++mt) {
        uint32_t ro = (arow + mt * 16) * RSTRIDE + akb;
        aHi[mt] = sbase + SM_AHI + ro;
        aLo[mt] = sbase + SM_ALO + ro;
    }
    // B x4: lanes 0-7: n0-7 k0 | 8-15: n0-7 k8 | 16-23: n8-15 k0 | 24-31: n8-15 k8
    const int brow = nw * 64 + (lane & 7) + (lane >> 4) * 8;
    const uint32_t bkb = ((lane >> 3) & 1) * 16;
    uint32_t bHi[4], bLo[4];
    #pragma unroll
    for (int q = 0; q < 4; ++q) {
        uint32_t ro = (brow + q * 16) * RSTRIDE + bkb;
        bHi[q] = sbase + SM_BHI + ro;
        bLo[q] = sbase + SM_BLO + ro;
    }

    float acc[2][8][4];
    #pragma unroll
    for (int mt = 0; mt < 2; ++mt)
        #pragma unroll
        for (int nt = 0; nt < 8; ++nt)
            #pragma unroll
            for (int c = 0; c < 4; ++c) acc[mt][nt][c] = 0.f;

    // ---- main loop: 8 k-steps of 16 ----
    #pragma unroll
    for (int kt = 0; kt < 8; ++kt) {
        const uint32_t ko = kt * 32;
        uint32_t ah[2][4], al[2][4], bh[4][4], bl[4][4];
        #pragma unroll
        for (int mt = 0; mt < 2; ++mt) {
            LDM4(ah[mt], aHi[mt] + ko);
            LDM4(al[mt], aLo[mt] + ko);
        }
        #pragma unroll
        for (int q = 0; q < 4; ++q) {
            LDM4(bh[q], bHi[q] + ko);
            LDM4(bl[q], bLo[q] + ko);
        }
        #pragma unroll
        for (int mt = 0; mt < 2; ++mt)
            #pragma unroll
            for (int nt = 0; nt < 8; ++nt) {
                const int q = nt >> 1, r = (nt & 1) * 2;
                MMA_BF16(acc[mt][nt], ah[mt], bh[q][r], bh[q][r + 1]);
                MMA_BF16(acc[mt][nt], ah[mt], bl[q][r], bl[q][r + 1]);
                MMA_BF16(acc[mt][nt], al[mt], bh[q][r], bh[q][r + 1]);
            }
    }

    // ---- epilogue ----
    #pragma unroll
    for (int mt = 0; mt < 2; ++mt)
        #pragma unroll
        for (int nt = 0; nt < 8; ++nt) {
            const float* c = acc[mt][nt];
            const int col = n0 + nw * 64 + nt * 8 + (lane & 3) * 2;
            const int r0  = m0 + mw * 32 + mt * 16 + (lane >> 2);
            float2 bv = *(const float2*)(bias + col);
            float2 lo = make_float2(c[0] + bv.x, c[1] + bv.y);
            float2 hi = make_float2(c[2] + bv.x, c[3] + bv.y);
            if (QKV) {
                const int s = col >> 7, hh2 = (col >> 5) & 3, d = col & 31;
                float* p0 = g_qkv + ((size_t)(s * 16 + b * 4 + hh2) * TOK + r0) * HD + d;
                *(float2*)p0 = lo;
                *(float2*)(p0 + 8 * HD) = hi;
            } else {
                float* p0 = outp + (size_t)r0 * EMBED + col;
                *(float2*)p0 = lo;
                *(float2*)(p0 + 8 * EMBED) = hi;
            }
        }
}

// ---------------- kernel 3: neighborhood attention ---------------------------
// R2/R4 layout (fp32 planar smem, conflict-free), with __expf replaced by a
// degree-8 expm1 Taylor polynomial on the FMA pipe: logits are tiny, and MUFU
// was co-limiting (~22us of SM-MUFU occupancy at 49 expf/thread).
#define TILE_I 8
#define TILE_J 16
#define HALO_I 14
#define HALO_J 22
#define NPOS   (HALO_I * HALO_J)        // 308 positions
#define NF4    (NPOS * 8)               // 2464 float4 per tensor
#define PLANE  1252                     // floats per plane, ==4 mod 32
#define ATTN_SMEM (8 * PLANE * 4)       // 40064 bytes

__global__ __launch_bounds__(128, 4) void attn_kernel() {
    extern __shared__ float smemf[];

    const int tid = threadIdx.x;
    const int z = blockIdx.z;             // b*4 + h
    const int b = z >> 2, h = z & 3;
    const int j0 = blockIdx.x * TILE_J;
    const int i0 = blockIdx.y * TILE_I;

    const int bh = b * 4 + h;
    const float* qg = g_qkv + (size_t)bh * TOK * HD;          // s=0
    const float* kg = g_qkv + (size_t)(16 + bh) * TOK * HD;   // s=1
    const float* vg = g_qkv + (size_t)(32 + bh) * TOK * HD;   // s=2

    const int li = tid >> 4;     // 0..7
    const int lj = tid & 15;     // 0..15
    const int gi = i0 + li, gj = j0 + lj;

    #pragma unroll 1
    for (int idx = tid; idx < NF4; idx += 128) {
        int pos = idx >> 3, f = idx & 7;
        int r = pos / HALO_J, c = pos - r * HALO_J;
        int ri = i0 - PAD + r, rj = j0 - PAD + c;
        float4 kv = make_float4(0.f, 0.f, 0.f, 0.f);
        if (ri >= 0 && ri < HH && rj >= 0 && rj < WW)
            kv = *(const float4*)(kg + ((size_t)(ri * WW + rj)) * HD + f * 4);
        *(float4*)(smemf + f * PLANE + pos * 4) = kv;
    }

    float4 rq[8];
    {
        const float4* qp = (const float4*)(qg + ((size_t)(gi * WW + gj)) * HD);
        #pragma unroll
        for (int q = 0; q < 8; ++q) {
            float4 v = qp[q];
            rq[q] = make_float4(v.x * SCALE, v.y * SCALE, v.z * SCALE, v.w * SCALE);
        }
    }
    __syncthreads();

    // ---- pass 1: logits -> p[49] = exp(logit) via FMA-pipe polynomial ----
    float p[K2];
    float den = 0.f;
    #pragma unroll
    for (int di = 0; di < KER; ++di) {
        #pragma unroll
        for (int dj = 0; dj < KER; ++dj) {
            const int pos4 = ((li + di) * HALO_J + (lj + dj)) * 4;
            float d0 = 0.f, d1 = 0.f, d2 = 0.f, d3 = 0.f;
            #pragma unroll
            for (int q = 0; q < 8; ++q) {
                float4 kv = *(const float4*)(smemf + q * PLANE + pos4);
                d0 = fmaf(rq[q].x, kv.x, d0);
                d1 = fmaf(rq[q].y, kv.y, d1);
                d2 = fmaf(rq[q].z, kv.z, d2);
                d3 = fmaf(rq[q].w, kv.w, d3);
            }
            const float xv = (d0 + d1) + (d2 + d3);
            // exp(x) = 1 + x*P(x), degree-8 Taylor (|x| small; rem < 1e-8)
            float t = fmaf(xv, 1.f / 40320.f, 1.f / 5040.f);
            t = fmaf(t, xv, 1.f / 720.f);
            t = fmaf(t, xv, 1.f / 120.f);
            t = fmaf(t, xv, 1.f / 24.f);
            t = fmaf(t, xv, 1.f / 6.f);
            t = fmaf(t, xv, 0.5f);
            t = fmaf(t, xv, 1.f);
            const float e = fmaf(xv, t, 1.f);
            p[di * KER + dj] = e;
            den += e;
        }
    }
    __syncthreads();   // everyone done reading K before overwrite

    #pragma unroll 1
    for (int idx = tid; idx < NF4; idx += 128) {
        int pos = idx >> 3, f = idx & 7;
        int r = pos / HALO_J, c = pos - r * HALO_J;
        int ri = i0 - PAD + r, rj = j0 - PAD + c;
        float4 vv = make_float4(0.f, 0.f, 0.f, 0.f);
        if (ri >= 0 && ri < HH && rj >= 0 && rj < WW)
            vv = *(const float4*)(vg + ((size_t)(ri * WW + rj)) * HD + f * 4);
        *(float4*)(smemf + f * PLANE + pos * 4) = vv;
    }
    __syncthreads();

    float4 acc[8];
    #pragma unroll
    for (int q = 0; q < 8; ++q) acc[q] = make_float4(0.f, 0.f, 0.f, 0.f);

    #pragma unroll
    for (int di = 0; di < KER; ++di) {
        #pragma unroll
        for (int dj = 0; dj < KER; ++dj) {
            const int pos4 = ((li + di) * HALO_J + (lj + dj)) * 4;
            const float pw = p[di * KER + dj];
            #pragma unroll
            for (int q = 0; q < 8; ++q) {
                float4 vv = *(const float4*)(smemf + q * PLANE + pos4);
                acc[q].x = fmaf(pw, vv.x, acc[q].x);
                acc[q].y = fmaf(pw, vv.y, acc[q].y);
                acc[q].z = fmaf(pw, vv.z, acc[q].z);
                acc[q].w = fmaf(pw, vv.w, acc[q].w);
            }
        }
    }

    const float inv = 1.f / den;
    float* op = g_attn + ((size_t)(b * TOK + gi * WW + gj)) * EMBED + h * HD;
    #pragma unroll
    for (int q = 0; q < 8; ++q) {
        float4 r = make_float4(acc[q].x * inv, acc[q].y * inv,
                               acc[q].z * inv, acc[q].w * inv);
        *(float4*)(op + q * 4) = r;
    }
}

// ---------------- launch -----------------------------------------------------
extern "C" void kernel_launch(void* const* d_in, const int* in_sizes, int n_in,
                              void* d_out, int out_size) {
    const float* x     = (const float*)d_in[0];
    const float* ctx   = (const float*)d_in[1];
    const float* Wqkv  = (const float*)d_in[2];
    const float* bqkv  = (const float*)d_in[3];
    const float* A     = (const float*)d_in[4];
    const float* Blora = (const float*)d_in[5];
    const float* Vlora = (const float*)d_in[6];
    const float* g1w   = (const float*)d_in[7];
    const float* g1b   = (const float*)d_in[8];
    const float* g2w   = (const float*)d_in[9];
    const float* g2b   = (const float*)d_in[10];
    const float* Wproj = (const float*)d_in[11];
    const float* bproj = (const float*)d_in[12];
    float* out = (float*)d_out;

    cudaFuncSetAttribute(attn_kernel,
                         cudaFuncAttributeMaxDynamicSharedMemorySize, ATTN_SMEM);
    cudaFuncSetAttribute(gemm_mma<true>,
                         cudaFuncAttributeMaxDynamicSharedMemorySize, GEMM_SMEM);
    cudaFuncSetAttribute(gemm_mma<false>,
                         cudaFuncAttributeMaxDynamicSharedMemorySize, GEMM_SMEM);

    prep_kernel<<<1, 128>>>(ctx, Blora, g1w, g1b, g2w, g2b);
    weff_kernel<<<768, 256>>>(Wqkv, A, Vlora);
    gemm_mma<true><<<dim3(32, 3, 4), 256, GEMM_SMEM>>>(x, nullptr, bqkv, nullptr);
    attn_kernel<<<dim3(WW / TILE_J, HH / TILE_I, NB * NH), 128, ATTN_SMEM>>>();
    gemm_mma<false><<<dim3(128, 1, 1), 256, GEMM_SMEM>>>(nullptr, Wproj, bproj, out);
}

// round 11
// speedup vs baseline: 1.4979x; 1.0021x over previous
#include <cuda_runtime.h>
#include <cuda_bf16.h>
#include <cuda_fp16.h>
#include <cstdint>

// Problem constants
#define NB     4
#define HH     64
#define WW     64
#define EMBED  128
#define NH     4
#define HD     32
#define CTX    256
#define RANK   8
#define KER    7
#define K2     49
#define PAD    3
#define SCALE  0.17677669529663689f   // 32^-0.5
#define TOK    4096                   // tokens per batch (64*64)
#define NTOK   16384                  // total tokens

// ---------------- device scratch (static allocation: allowed) ----------------
__device__ float g_c2[NB * RANK];                 // alpha_b * c_proj[b][r]
__device__ float g_Weff[NB * 3 * EMBED * EMBED];  // [b][o][i]
__device__ float g_qkv[3 * NB * NH * TOK * HD];   // [s][b][h][tok][d]
__device__ float g_attn[NTOK * EMBED];            // [tok][h*32+d]

// ---------------- kernel 0: c2 = alpha * (context @ Blora) -------------------
__global__ void prep_kernel(const float* __restrict__ ctx,
                            const float* __restrict__ Blora,
                            const float* __restrict__ g1w,
                            const float* __restrict__ g1b,
                            const float* __restrict__ g2w,
                            const float* __restrict__ g2b) {
    __shared__ float scp[32];
    __shared__ float sh[64];
    __shared__ float sal[4];
    int t = threadIdx.x;
    if (t < 32) {
        int b = t >> 3, r = t & 7;
        float s = 0.f;
        #pragma unroll 4
        for (int c = 0; c < CTX; ++c)
            s = fmaf(ctx[b * CTX + c], Blora[c * RANK + r], s);
        scp[t] = s;
    } else if (t >= 64) {
        int u = t - 64;
        int b = u >> 4, j = u & 15;
        float hj = g1b[j];
        #pragma unroll 4
        for (int c = 0; c < CTX; ++c)
            hj = fmaf(ctx[b * CTX + c], g1w[j * CTX + c], hj);
        sh[u] = fmaxf(hj, 0.f) * g2w[j];
    }
    __syncthreads();
    if (t < 4) {
        float s = g2b[0];
        #pragma unroll
        for (int j = 0; j < 16; ++j) s += sh[t * 16 + j];
        sal[t] = 1.f / (1.f + __expf(-s));
    }
    __syncthreads();
    if (t < 32) g_c2[t] = sal[t >> 3] * scp[t];
}

// ---------------- kernel 1: W_eff = Wqkv + Vlora diag(c2) A^T ----------------
__global__ void weff_kernel(const float* __restrict__ Wqkv,
                            const float* __restrict__ A,
                            const float* __restrict__ Vl) {
    int idx = blockIdx.x * 256 + threadIdx.x;     // 4*384*128 = 196608 total
    int b = idx / (3 * EMBED * EMBED);
    int rem = idx - b * (3 * EMBED * EMBED);
    int o = rem >> 7, i = rem & 127;
    float w = Wqkv[rem];
    const float* c2 = g_c2 + b * RANK;
    #pragma unroll
    for (int r = 0; r < RANK; ++r)
        w = fmaf(Vl[o * RANK + r] * c2[r], A[i * RANK + r], w);
    g_Weff[idx] = w;
}

// ================== bf16x3 tensor-core GEMM (mma.sync path) ==================
#define RSTRIDE 272
#define SM_AHI  0
#define SM_ALO  (128 * RSTRIDE)
#define SM_BHI  (2 * 128 * RSTRIDE)
#define SM_BLO  (3 * 128 * RSTRIDE)
#define GEMM_SMEM (4 * 128 * RSTRIDE)   // 139264 bytes

__device__ __forceinline__ uint32_t smem_u32(const void* p) {
    uint32_t a;
    asm("{ .reg .u64 t; cvta.to.shared.u64 t, %1; cvt.u32.u64 %0, t; }"
        : "=r"(a) : "l"(p));
    return a;
}

#define LDM4(r, addr) \
    asm volatile("ldmatrix.sync.aligned.m8n8.x4.shared.b16 {%0,%1,%2,%3}, [%4];" \
        : "=r"((r)[0]), "=r"((r)[1]), "=r"((r)[2]), "=r"((r)[3]) : "r"(addr))

#define MMA_BF16(c, a, b0, b1) \
    asm volatile("mma.sync.aligned.m16n8k16.row.col.f32.bf16.bf16.f32 " \
        "{%0,%1,%2,%3}, {%4,%5,%6,%7}, {%8,%9}, {%0,%1,%2,%3};" \
        : "+f"((c)[0]), "+f"((c)[1]), "+f"((c)[2]), "+f"((c)[3]) \
        : "r"((a)[0]), "r"((a)[1]), "r"((a)[2]), "r"((a)[3]), "r"(b0), "r"(b1))

// split one float into (hi, lo) bf16 and pack pairs into u32s
__device__ __forceinline__ void split2(float x, float y, uint32_t& hi, uint32_t& lo) {
    __nv_bfloat16 hx = __float2bfloat16_rn(x);
    __nv_bfloat16 hy = __float2bfloat16_rn(y);
    __nv_bfloat16 lx = __float2bfloat16_rn(x - __bfloat162float(hx));
    __nv_bfloat16 ly = __float2bfloat16_rn(y - __bfloat162float(hy));
    hi = ((uint32_t)__bfloat16_as_ushort(hy) << 16) | __bfloat16_as_ushort(hx);
    lo = ((uint32_t)__bfloat16_as_ushort(ly) << 16) | __bfloat16_as_ushort(lx);
}

template <bool QKV>
__global__ __launch_bounds__(256, 1)
void gemm_mma(const float* __restrict__ Aglob,
              const float* __restrict__ Wglob,
              const float* __restrict__ bias,
              float* __restrict__ outp) {
    extern __shared__ char smem[];
    const uint32_t sbase = smem_u32(smem);
    const int tid  = threadIdx.x;
    const int wid  = tid >> 5;
    const int lane = tid & 31;
    const int mw = wid >> 1;          // 0..3
    const int nw = wid & 1;           // 0..1
    const int b  = blockIdx.z;
    const int m0 = blockIdx.x * 128;
    const int n0 = blockIdx.y * 128;

    const float* srcA = QKV ? Aglob + ((size_t)b * TOK + m0) * EMBED
                            : g_attn + (size_t)m0 * EMBED;
    const float* srcB = QKV ? g_Weff + (size_t)b * 3 * EMBED * EMBED + (size_t)n0 * EMBED
                            : Wglob + (size_t)n0 * EMBED;

    // ---- fill A/B tiles: fp32 -> (hi, lo) bf16 planes, 272B row stride ----
    #pragma unroll
    for (int it = 0; it < 16; ++it) {
        int idx = it * 256 + tid;            // 4096 float4 slots
        int row = idx >> 5, c4 = idx & 31;
        float4 v = *(const float4*)(srcA + (size_t)row * EMBED + c4 * 4);
        uint32_t h0, l0, h1, l1;
        split2(v.x, v.y, h0, l0);
        split2(v.z, v.w, h1, l1);
        uint32_t off = row * RSTRIDE + c4 * 8;
        *(uint2*)(smem + SM_AHI + off) = make_uint2(h0, h1);
        *(uint2*)(smem + SM_ALO + off) = make_uint2(l0, l1);
    }
    #pragma unroll
    for (int it = 0; it < 16; ++it) {
        int idx = it * 256 + tid;
        int row = idx >> 5, c4 = idx & 31;
        float4 v = *(const float4*)(srcB + (size_t)row * EMBED + c4 * 4);
        uint32_t h0, l0, h1, l1;
        split2(v.x, v.y, h0, l0);
        split2(v.z, v.w, h1, l1);
        uint32_t off = row * RSTRIDE + c4 * 8;
        *(uint2*)(smem + SM_BHI + off) = make_uint2(h0, h1);
        *(uint2*)(smem + SM_BLO + off) = make_uint2(l0, l1);
    }
    __syncthreads();

    const int arow = mw * 32 + (lane & 7) + ((lane >> 3) & 1) * 8;
    const uint32_t akb = ((lane >> 4) & 1) * 16;
    uint32_t aHi[2], aLo[2];
    #pragma unroll
    for (int mt = 0; mt < 2; ++mt) {
        uint32_t ro = (arow + mt * 16) * RSTRIDE + akb;
        aHi[mt] = sbase + SM_AHI + ro;
        aLo[mt] = sbase + SM_ALO + ro;
    }
    const int brow = nw * 64 + (lane & 7) + (lane >> 4) * 8;
    const uint32_t bkb = ((lane >> 3) & 1) * 16;
    uint32_t bHi[4], bLo[4];
    #pragma unroll
    for (int q = 0; q < 4; ++q) {
        uint32_t ro = (brow + q * 16) * RSTRIDE + bkb;
        bHi[q] = sbase + SM_BHI + ro;
        bLo[q] = sbase + SM_BLO + ro;
    }

    float acc[2][8][4];
    #pragma unroll
    for (int mt = 0; mt < 2; ++mt)
        #pragma unroll
        for (int nt = 0; nt < 8; ++nt)
            #pragma unroll
            for (int c = 0; c < 4; ++c) acc[mt][nt][c] = 0.f;

    #pragma unroll
    for (int kt = 0; kt < 8; ++kt) {
        const uint32_t ko = kt * 32;
        uint32_t ah[2][4], al[2][4], bh[4][4], bl[4][4];
        #pragma unroll
        for (int mt = 0; mt < 2; ++mt) {
            LDM4(ah[mt], aHi[mt] + ko);
            LDM4(al[mt], aLo[mt] + ko);
        }
        #pragma unroll
        for (int q = 0; q < 4; ++q) {
            LDM4(bh[q], bHi[q] + ko);
            LDM4(bl[q], bLo[q] + ko);
        }
        #pragma unroll
        for (int mt = 0; mt < 2; ++mt)
            #pragma unroll
            for (int nt = 0; nt < 8; ++nt) {
                const int q = nt >> 1, r = (nt & 1) * 2;
                MMA_BF16(acc[mt][nt], ah[mt], bh[q][r], bh[q][r + 1]);
                MMA_BF16(acc[mt][nt], ah[mt], bl[q][r], bl[q][r + 1]);
                MMA_BF16(acc[mt][nt], al[mt], bh[q][r], bh[q][r + 1]);
            }
    }

    #pragma unroll
    for (int mt = 0; mt < 2; ++mt)
        #pragma unroll
        for (int nt = 0; nt < 8; ++nt) {
            const float* c = acc[mt][nt];
            const int col = n0 + nw * 64 + nt * 8 + (lane & 3) * 2;
            const int r0  = m0 + mw * 32 + mt * 16 + (lane >> 2);
            float2 bv = *(const float2*)(bias + col);
            float2 lo = make_float2(c[0] + bv.x, c[1] + bv.y);
            float2 hi = make_float2(c[2] + bv.x, c[3] + bv.y);
            if (QKV) {
                const int s = col >> 7, hh2 = (col >> 5) & 3, d = col & 31;
                float* p0 = g_qkv + ((size_t)(s * 16 + b * 4 + hh2) * TOK + r0) * HD + d;
                *(float2*)p0 = lo;
                *(float2*)(p0 + 8 * HD) = hi;
            } else {
                float* p0 = outp + (size_t)r0 * EMBED + col;
                *(float2*)p0 = lo;
                *(float2*)(p0 + 8 * EMBED) = hi;
            }
        }
}

// ---------------- kernel 3: neighborhood attention (split-query) -------------
// Tile 8x8 queries, grid 1024 CTAs (~6.9/SM). 128 threads = 64 queries x 2
// half-dim threads (16 dims each). Logit = partial dot + shfl_xor(1).
// Halo 14x14, fp32 planar smem (8 planes of float4-chunks), PLANE=804
// (==4 mod 8) => every 8-lane LDS/STS phase spans 32 distinct banks.
// One buffer reused K then V; softmax weights u=exp(x)-1 in fp16 pairs.
#define TILE_Q 8
#define HALO_Q 14
#define NPOS_A (HALO_Q * HALO_Q)        // 196 positions
#define NF4_A  (NPOS_A * 8)             // 1568 float4 per tensor
#define PLANE  804                      // floats per plane (196*4=784 + pad)
#define ATTN_SMEM (8 * PLANE * 4)       // 25728 bytes

__device__ __forceinline__ __half2 u2h(uint32_t u) {
    __half2 h; *(uint32_t*)&h = u; return h;
}

__global__ __launch_bounds__(128, 6) void attn_kernel() {
    extern __shared__ float smemf[];

    const int tid = threadIdx.x;
    const int z = blockIdx.z;             // b*4 + h
    const int b = z >> 2, h = z & 3;
    const int j0 = blockIdx.x * TILE_Q;
    const int i0 = blockIdx.y * TILE_Q;

    const int bh = b * 4 + h;
    const float* qg = g_qkv + (size_t)bh * TOK * HD;          // s=0
    const float* kg = g_qkv + (size_t)(16 + bh) * TOK * HD;   // s=1
    const float* vg = g_qkv + (size_t)(32 + bh) * TOK * HD;   // s=2

    const int half = tid & 1;            // which 16 dims
    const int q    = tid >> 1;           // query 0..63
    const int qi = q >> 3, qj = q & 7;
    const int gi = i0 + qi, gj = j0 + qj;
    const int pbase = half * 4;          // first plane for this half

    // ---- fill K halo (zero OOB == reference zero-padding) ----
    #pragma unroll 1
    for (int idx = tid; idx < NF4_A; idx += 128) {
        int pos = idx >> 3, f = idx & 7;
        int r = pos / HALO_Q, c = pos - r * HALO_Q;
        int ri = i0 - PAD + r, rj = j0 - PAD + c;
        float4 kv = make_float4(0.f, 0.f, 0.f, 0.f);
        if (ri >= 0 && ri < HH && rj >= 0 && rj < WW)
            kv = *(const float4*)(kg + ((size_t)(ri * WW + rj)) * HD + f * 4);
        *(float4*)(smemf + f * PLANE + pos * 4) = kv;
    }

    // q: this thread's 16 dims, SCALE folded
    float4 rq[4];
    {
        const float4* qp = (const float4*)(qg + ((size_t)(gi * WW + gj)) * HD + half * 16);
        #pragma unroll
        for (int k = 0; k < 4; ++k) {
            float4 v = qp[k];
            rq[k] = make_float4(v.x * SCALE, v.y * SCALE, v.z * SCALE, v.w * SCALE);
        }
    }
    __syncthreads();

    // ---- pass 1: partial dots + shfl combine -> u = expm1(logit), fp16 ----
    __half2 uu[25];
    float su = 0.f;
    float upend = 0.f;
    #pragma unroll
    for (int di = 0; di < KER; ++di) {
        #pragma unroll
        for (int dj = 0; dj < KER; ++dj) {
            const int pos4 = ((qi + di) * HALO_Q + (qj + dj)) * 4;
            float d0 = 0.f, d1 = 0.f, d2 = 0.f, d3 = 0.f;
            #pragma unroll
            for (int k = 0; k < 4; ++k) {
                float4 kv = *(const float4*)(smemf + (pbase + k) * PLANE + pos4);
                d0 = fmaf(rq[k].x, kv.x, d0);
                d1 = fmaf(rq[k].y, kv.y, d1);
                d2 = fmaf(rq[k].z, kv.z, d2);
                d3 = fmaf(rq[k].w, kv.w, d3);
            }
            const float xp = (d0 + d1) + (d2 + d3);
            const float xv = xp + __shfl_xor_sync(0xffffffffu, xp, 1);
            // expm1 via degree-8 Taylor (|x| small): u = x * P(x)
            float t = fmaf(xv, 1.f / 40320.f, 1.f / 5040.f);
            t = fmaf(t, xv, 1.f / 720.f);
            t = fmaf(t, xv, 1.f / 120.f);
            t = fmaf(t, xv, 1.f / 24.f);
            t = fmaf(t, xv, 1.f / 6.f);
            t = fmaf(t, xv, 0.5f);
            t = fmaf(t, xv, 1.f);
            const float u = xv * t;
            su += u;
            const int idx = di * KER + dj;
            if ((idx & 1) == 0) upend = u;
            else uu[idx >> 1] = __floats2half2_rn(upend, u);
        }
    }
    uu[24] = __floats2half2_rn(upend, 0.f);
    __syncthreads();   // done reading K before overwrite

    // ---- fill V halo (same buffer) ----
    #pragma unroll 1
    for (int idx = tid; idx < NF4_A; idx += 128) {
        int pos = idx >> 3, f = idx & 7;
        int r = pos / HALO_Q, c = pos - r * HALO_Q;
        int ri = i0 - PAD + r, rj = j0 - PAD + c;
        float4 vv = make_float4(0.f, 0.f, 0.f, 0.f);
        if (ri >= 0 && ri < HH && rj >= 0 && rj < WW)
            vv = *(const float4*)(vg + ((size_t)(ri * WW + rj)) * HD + f * 4);
        *(float4*)(smemf + f * PLANE + pos * 4) = vv;
    }
    __syncthreads();

    // ---- pass 2: out = sum (1+u) * v over this thread's 16 dims ----
    float4 acc[4];
    #pragma unroll
    for (int k = 0; k < 4; ++k) acc[k] = make_float4(0.f, 0.f, 0.f, 0.f);

    #pragma unroll
    for (int di = 0; di < KER; ++di) {
        #pragma unroll
        for (int dj = 0; dj < KER; ++dj) {
            const int idx = di * KER + dj;
            const __half2 up = uu[idx >> 1];
            const float pw = 1.f + ((idx & 1) ? __high2float(up) : __low2float(up));
            const int pos4 = ((qi + di) * HALO_Q + (qj + dj)) * 4;
            #pragma unroll
            for (int k = 0; k < 4; ++k) {
                float4 vv = *(const float4*)(smemf + (pbase + k) * PLANE + pos4);
                acc[k].x = fmaf(pw, vv.x, acc[k].x);
                acc[k].y = fmaf(pw, vv.y, acc[k].y);
                acc[k].z = fmaf(pw, vv.z, acc[k].z);
                acc[k].w = fmaf(pw, vv.w, acc[k].w);
            }
        }
    }

    const float inv = 1.f / (49.f + su);
    float* op = g_attn + ((size_t)(b * TOK + gi * WW + gj)) * EMBED + h * HD + half * 16;
    #pragma unroll
    for (int k = 0; k < 4; ++k) {
        float4 r = make_float4(acc[k].x * inv, acc[k].y * inv,
                               acc[k].z * inv, acc[k].w * inv);
        *(float4*)(op + k * 4) = r;
    }
}

// ---------------- launch -----------------------------------------------------
extern "C" void kernel_launch(void* const* d_in, const int* in_sizes, int n_in,
                              void* d_out, int out_size) {
    const float* x     = (const float*)d_in[0];
    const float* ctx   = (const float*)d_in[1];
    const float* Wqkv  = (const float*)d_in[2];
    const float* bqkv  = (const float*)d_in[3];
    const float* A     = (const float*)d_in[4];
    const float* Blora = (const float*)d_in[5];
    const float* Vlora = (const float*)d_in[6];
    const float* g1w   = (const float*)d_in[7];
    const float* g1b   = (const float*)d_in[8];
    const float* g2w   = (const float*)d_in[9];
    const float* g2b   = (const float*)d_in[10];
    const float* Wproj = (const float*)d_in[11];
    const float* bproj = (const float*)d_in[12];
    float* out = (float*)d_out;

    cudaFuncSetAttribute(gemm_mma<true>,
                         cudaFuncAttributeMaxDynamicSharedMemorySize, GEMM_SMEM);
    cudaFuncSetAttribute(gemm_mma<false>,
                         cudaFuncAttributeMaxDynamicSharedMemorySize, GEMM_SMEM);

    prep_kernel<<<1, 128>>>(ctx, Blora, g1w, g1b, g2w, g2b);
    weff_kernel<<<768, 256>>>(Wqkv, A, Vlora);
    gemm_mma<true><<<dim3(32, 3, 4), 256, GEMM_SMEM>>>(x, nullptr, bqkv, nullptr);
    attn_kernel<<<dim3(WW / TILE_Q, HH / TILE_Q, NB * NH), 128, ATTN_SMEM>>>();
    gemm_mma<false><<<dim3(128, 1, 1), 256, GEMM_SMEM>>>(nullptr, Wproj, bproj, out);
}